// round 3
// baseline (speedup 1.0000x reference)
#include <cuda_runtime.h>

// Quaternion power unit:
//   per token t (2048), per out o (128):
//     theta[o,c] = w[o,c]*acos(clip(r[c])) + b[o]
//     q_c = (cos th, v_hat_c * sin th),  v_hat = (i,j,k)/sqrt(i^2+j^2+k^2+eps)
//     P = q_0 * q_1 * ... * q_63  (Hamilton, associative -> any order)
//     out = P / |P|
//
// Strategy: pure fp32-pipe problem. Use packed f32x2 (FFMA2) — each thread
// computes TWO adjacent outputs; all per-channel token data is shared between
// the pair, so the Hamilton chain runs at 2 outs per instruction.

#define CIN 64
#define COUT 128
#define TPB_TOKENS 4
#define NTHREADS 256  // 4 token-groups x 64 lanes

typedef unsigned long long u64;

__device__ __forceinline__ u64 pk2(float lo, float hi) {
    u64 r; asm("mov.b64 %0, {%1, %2};" : "=l"(r) : "f"(lo), "f"(hi)); return r;
}
__device__ __forceinline__ void up2(u64 v, float& lo, float& hi) {
    asm("mov.b64 {%0, %1}, %2;" : "=f"(lo), "=f"(hi) : "l"(v));
}
__device__ __forceinline__ u64 f2fma(u64 a, u64 b, u64 c) {
    u64 d; asm("fma.rn.f32x2 %0, %1, %2, %3;" : "=l"(d) : "l"(a), "l"(b), "l"(c)); return d;
}
__device__ __forceinline__ u64 f2mul(u64 a, u64 b) {
    u64 d; asm("mul.rn.f32x2 %0, %1, %2;" : "=l"(d) : "l"(a), "l"(b)); return d;
}

__global__ __launch_bounds__(NTHREADS)
void qpu_kernel(const float* __restrict__ x, const float* __restrict__ w,
                const float* __restrict__ bias, float* __restrict__ out,
                int n_tokens)
{
    // weight staged interleaved: sw[c][lane] = {w[2*lane][c], w[2*lane+1][c]}  (32 KB)
    __shared__ __align__(16) u64 sw[CIN][CIN];
    // per-token precomputed, pre-duplicated into both f32x2 lanes:
    //   tok[g][c] = { {th,th}, {iv,iv}, {jv,jv}, {kv,kv} }                     (8 KB)
    __shared__ __align__(16) u64 tok[TPB_TOKENS][CIN][4];

    const int tid  = threadIdx.x;
    const int g    = tid >> 6;
    const int lane = tid & 63;

    // ---- stage weight into shared (once per block, reused by 4 tokens) ----
    for (int idx = tid; idx < CIN * CIN; idx += NTHREADS) {
        int c = idx >> 6, l = idx & 63;
        float w0 = w[(2 * l) * CIN + c];
        float w1 = w[(2 * l + 1) * CIN + c];
        sw[c][l] = pk2(w0, w1);
    }

    const int tokIdx = blockIdx.x * TPB_TOKENS + g;

    // ---- per-token preprocessing: one channel per lane ----
    if (tokIdx < n_tokens) {
        const float* xp = x + (size_t)tokIdx * (4 * CIN);
        int c = lane;
        float r = xp[c];
        float i = xp[CIN + c];
        float j = xp[2 * CIN + c];
        float k = xp[3 * CIN + c];
        float inv = rsqrtf(fmaf(i, i, fmaf(j, j, fmaf(k, k, 1e-12f))));
        const float CLAMP = (float)(1.0 - 1e-6);
        r = fminf(fmaxf(r, -CLAMP), CLAMP);
        float th = acosf(r);
        float iv = i * inv, jv = j * inv, kv = k * inv;
        tok[g][c][0] = pk2(th, th);
        tok[g][c][1] = pk2(iv, iv);
        tok[g][c][2] = pk2(jv, jv);
        tok[g][c][3] = pk2(kv, kv);
    }
    __syncthreads();

    if (tokIdx >= n_tokens) return;

    // ---- main chain: this thread owns outs (2*lane, 2*lane+1), packed f32x2 ----
    const u64 bias2 = ((const u64*)bias)[lane];  // {b[2l], b[2l+1]} contiguous

    u64 ar = pk2(1.0f, 1.0f);  // identity quaternion
    u64 ai = 0ull, aj = 0ull, ak = 0ull;
    const u64 SGN = 0x8000000080000000ull;

#pragma unroll 8
    for (int c = 0; c < CIN; ++c) {
        ulonglong2 t01 = *(const ulonglong2*)(&tok[g][c][0]);  // {thth, iviv}
        ulonglong2 t23 = *(const ulonglong2*)(&tok[g][c][2]);  // {jvjv, kvkv}
        u64 w2 = sw[c][lane];

        u64 th2 = f2fma(w2, t01.x, bias2);  // theta pair
        float t0, t1; up2(th2, t0, t1);
        float s0, c0, s1, c1;
        __sincosf(t0, &s0, &c0);
        __sincosf(t1, &s1, &c1);
        u64 sin2 = pk2(s0, s1);
        u64 qr   = pk2(c0, c1);
        u64 qi = f2mul(t01.y, sin2);
        u64 qj = f2mul(t23.x, sin2);
        u64 qk = f2mul(t23.y, sin2);
        u64 mqi = qi ^ SGN, mqj = qj ^ SGN, mqk = qk ^ SGN;

        // acc = acc (x) q   (Hamilton), 16 FFMA2
        u64 nr = f2fma(ar, qr, f2fma(ai, mqi, f2fma(aj, mqj, f2mul(ak, mqk))));
        u64 ni = f2fma(ar, qi, f2fma(ai, qr,  f2fma(aj, qk,  f2mul(ak, mqj))));
        u64 nj = f2fma(ar, qj, f2fma(ai, mqk, f2fma(aj, qr,  f2mul(ak, qi))));
        u64 nk = f2fma(ar, qk, f2fma(ai, qj,  f2fma(aj, mqi, f2mul(ak, qr))));
        ar = nr; ai = ni; aj = nj; ak = nk;
    }

    // ---- normalize + store ----
    u64 eps2 = pk2(1e-12f, 1e-12f);
    u64 n2 = f2fma(ar, ar, f2fma(ai, ai, f2fma(aj, aj, f2fma(ak, ak, eps2))));
    float n0, n1; up2(n2, n0, n1);
    u64 inv2 = pk2(rsqrtf(n0), rsqrtf(n1));

    u64 orr = f2mul(ar, inv2);
    u64 oii = f2mul(ai, inv2);
    u64 ojj = f2mul(aj, inv2);
    u64 okk = f2mul(ak, inv2);

    float2* ob = (float2*)(out + (size_t)tokIdx * (4 * COUT));
    ob[lane]           = *(float2*)&orr;   // pr
    ob[64 + lane]      = *(float2*)&oii;   // pi
    ob[128 + lane]     = *(float2*)&ojj;   // pj
    ob[192 + lane]     = *(float2*)&okk;   // pk
}

extern "C" void kernel_launch(void* const* d_in, const int* in_sizes, int n_in,
                              void* d_out, int out_size) {
    const float* x = (const float*)d_in[0];
    const float* w = (const float*)d_in[1];
    const float* b = (const float*)d_in[2];
    int tokens = in_sizes[0] / (4 * CIN);
    int grid = (tokens + TPB_TOKENS - 1) / TPB_TOKENS;
    qpu_kernel<<<grid, NTHREADS>>>(x, w, b, (float*)d_out, tokens);
}

// round 7
// speedup vs baseline: 1.0157x; 1.0157x over previous
#include <cuda_runtime.h>

// Quaternion power unit, split-chain version:
//   Each (token, out-pair) is handled by TWO threads: half h owns channels
//   [32h, 32h+32), folds them into a partial Hamilton product, then the pair
//   merges via shfl_xor(16) + one Hamilton product (associativity preserves
//   the left-to-right order). Packed f32x2 (FFMA2) throughout: each thread
//   still computes TWO adjacent outputs per instruction.

#define CIN 64
#define COUT 128
#define TPB_TOKENS 4
#define NTHREADS 512  // 4 tokens x 128 lanes (64 out-pairs x 2 halves)

typedef unsigned long long u64;

__device__ __forceinline__ u64 pk2(float lo, float hi) {
    u64 r; asm("mov.b64 %0, {%1, %2};" : "=l"(r) : "f"(lo), "f"(hi)); return r;
}
__device__ __forceinline__ void up2(u64 v, float& lo, float& hi) {
    asm("mov.b64 {%0, %1}, %2;" : "=f"(lo), "=f"(hi) : "l"(v));
}
__device__ __forceinline__ u64 f2fma(u64 a, u64 b, u64 c) {
    u64 d; asm("fma.rn.f32x2 %0, %1, %2, %3;" : "=l"(d) : "l"(a), "l"(b), "l"(c)); return d;
}
__device__ __forceinline__ u64 f2mul(u64 a, u64 b) {
    u64 d; asm("mul.rn.f32x2 %0, %1, %2;" : "=l"(d) : "l"(a), "l"(b)); return d;
}

__global__ __launch_bounds__(NTHREADS)
void qpu_kernel(const float* __restrict__ x, const float* __restrict__ w,
                const float* __restrict__ bias, float* __restrict__ out,
                int n_tokens)
{
    // sw[c][opair] = {w[2*opair][c], w[2*opair+1][c]}   (32 KB)
    __shared__ __align__(16) u64 sw[CIN][CIN];
    // tok[g][c] = { {th,th}, {iv,iv}, {jv,jv}, {kv,kv} } (8 KB)
    __shared__ __align__(16) u64 tok[TPB_TOKENS][CIN][4];

    const int tid  = threadIdx.x;
    const int g    = tid >> 7;              // token within block (0..3)
    const int lt   = tid & 127;             // lane within token
    // warp layout: threads 0-15 = half 0, 16-31 = half 1, same 16 out-pairs.
    const int opair = ((lt >> 5) << 4) | (lt & 15);  // 0..63
    const int half  = (lt >> 4) & 1;

    // ---- stage weight into shared (once per block) ----
    for (int idx = tid; idx < CIN * CIN; idx += NTHREADS) {
        int c = idx >> 6, l = idx & 63;
        sw[c][l] = pk2(w[(2 * l) * CIN + c], w[(2 * l + 1) * CIN + c]);
    }

    const int tokIdx = blockIdx.x * TPB_TOKENS + g;

    // ---- per-token preprocessing: one channel per lane (lanes 0..63) ----
    if (tokIdx < n_tokens && lt < CIN) {
        const float* xp = x + (size_t)tokIdx * (4 * CIN);
        int c = lt;
        float r = xp[c];
        float i = xp[CIN + c];
        float j = xp[2 * CIN + c];
        float k = xp[3 * CIN + c];
        float inv = rsqrtf(fmaf(i, i, fmaf(j, j, fmaf(k, k, 1e-12f))));
        const float CLAMP = (float)(1.0 - 1e-6);
        r = fminf(fmaxf(r, -CLAMP), CLAMP);
        float th = acosf(r);
        tok[g][c][0] = pk2(th, th);
        tok[g][c][1] = pk2(i * inv, i * inv);
        tok[g][c][2] = pk2(j * inv, j * inv);
        tok[g][c][3] = pk2(k * inv, k * inv);
    }
    __syncthreads();

    if (tokIdx >= n_tokens) return;

    const u64 bias2 = ((const u64*)bias)[opair];  // {b[2p], b[2p+1]}

    u64 ar = pk2(1.0f, 1.0f);  // identity
    u64 ai = 0ull, aj = 0ull, ak = 0ull;
    const u64 SGN = 0x8000000080000000ull;
    const int cbase = half << 5;   // 0 or 32

#pragma unroll 8
    for (int cc = 0; cc < CIN / 2; ++cc) {
        const int c = cbase + cc;
        ulonglong2 t01 = *(const ulonglong2*)(&tok[g][c][0]);  // {thth, iviv}
        ulonglong2 t23 = *(const ulonglong2*)(&tok[g][c][2]);  // {jvjv, kvkv}
        u64 w2 = sw[c][opair];

        u64 th2 = f2fma(w2, t01.x, bias2);
        float t0, t1; up2(th2, t0, t1);
        float s0, c0, s1, c1;
        __sincosf(t0, &s0, &c0);
        __sincosf(t1, &s1, &c1);
        u64 sin2 = pk2(s0, s1);
        u64 qr   = pk2(c0, c1);
        u64 qi = f2mul(t01.y, sin2);
        u64 qj = f2mul(t23.x, sin2);
        u64 qk = f2mul(t23.y, sin2);
        u64 mqi = qi ^ SGN, mqj = qj ^ SGN, mqk = qk ^ SGN;

        u64 nr = f2fma(ar, qr, f2fma(ai, mqi, f2fma(aj, mqj, f2mul(ak, mqk))));
        u64 ni = f2fma(ar, qi, f2fma(ai, qr,  f2fma(aj, qk,  f2mul(ak, mqj))));
        u64 nj = f2fma(ar, qj, f2fma(ai, mqk, f2fma(aj, qr,  f2mul(ak, qi))));
        u64 nk = f2fma(ar, qk, f2fma(ai, qj,  f2fma(aj, mqi, f2mul(ak, qr))));
        ar = nr; ai = ni; aj = nj; ak = nk;
    }

    // ---- merge halves: P = P_half0 (x) P_half1 via shfl_xor(16) ----
    u64 br = __shfl_xor_sync(0xFFFFFFFFu, ar, 16);
    u64 bi = __shfl_xor_sync(0xFFFFFFFFu, ai, 16);
    u64 bj = __shfl_xor_sync(0xFFFFFFFFu, aj, 16);
    u64 bk = __shfl_xor_sync(0xFFFFFFFFu, ak, 16);

    // half 0: A = mine, B = other ; half 1: A = other, B = mine
    u64 Ar = half ? br : ar,  Ai = half ? bi : ai;
    u64 Aj = half ? bj : aj,  Ak = half ? bk : ak;
    u64 Br = half ? ar : br,  Bi = half ? ai : bi;
    u64 Bj = half ? aj : bj,  Bk = half ? ak : bk;

    u64 pr = f2fma(Ar, Br, f2fma(Ai, Bi ^ SGN, f2fma(Aj, Bj ^ SGN, f2mul(Ak, Bk ^ SGN))));
    u64 pi = f2fma(Ar, Bi, f2fma(Ai, Br,       f2fma(Aj, Bk,       f2mul(Ak, Bj ^ SGN))));
    u64 pj = f2fma(Ar, Bj, f2fma(Ai, Bk ^ SGN, f2fma(Aj, Br,       f2mul(Ak, Bi))));
    u64 pk_ = f2fma(Ar, Bk, f2fma(Ai, Bj,      f2fma(Aj, Bi ^ SGN, f2mul(Ak, Br))));

    // ---- normalize ----
    u64 eps2 = pk2(1e-12f, 1e-12f);
    u64 n2 = f2fma(pr, pr, f2fma(pi, pi, f2fma(pj, pj, f2fma(pk_, pk_, eps2))));
    float n0, n1; up2(n2, n0, n1);
    u64 inv2 = pk2(rsqrtf(n0), rsqrtf(n1));

    float2* ob = (float2*)(out + (size_t)tokIdx * (4 * COUT));
    if (half == 0) {
        u64 v0 = f2mul(pr, inv2);
        u64 v1 = f2mul(pi, inv2);
        ob[opair]       = *(float2*)&v0;   // pr
        ob[64 + opair]  = *(float2*)&v1;   // pi
    } else {
        u64 v2 = f2mul(pj, inv2);
        u64 v3 = f2mul(pk_, inv2);
        ob[128 + opair] = *(float2*)&v2;   // pj
        ob[192 + opair] = *(float2*)&v3;   // pk
    }
}

extern "C" void kernel_launch(void* const* d_in, const int* in_sizes, int n_in,
                              void* d_out, int out_size) {
    const float* x = (const float*)d_in[0];
    const float* w = (const float*)d_in[1];
    const float* b = (const float*)d_in[2];
    int tokens = in_sizes[0] / (4 * CIN);
    int grid = (tokens + TPB_TOKENS - 1) / TPB_TOKENS;
    qpu_kernel<<<grid, NTHREADS>>>(x, w, b, (float*)d_out, tokens);
}

// round 9
// speedup vs baseline: 1.0241x; 1.0083x over previous
#include <cuda_runtime.h>

// Quaternion power unit — LDS-diet + dual-chain version.
//   Layout as R3: token group of 128 lanes = 64 out-pairs x 2 halves; half h
//   owns channels [32h,32h+32). NEW: each thread folds its 32 channels as TWO
//   independent Hamilton chains (16+16, contiguous) merged at the end, and the
//   token data is ONE float4 LDS.128 per channel (was two LDS.128), with theta
//   computed by scalar FFMAs straight from the weight pair (no pack/unpack).

#define CIN 64
#define COUT 128
#define TPB_TOKENS 4
#define NTHREADS 512  // 4 tokens x 128 lanes

typedef unsigned long long u64;

__device__ __forceinline__ u64 pk2(float lo, float hi) {
    u64 r; asm("mov.b64 %0, {%1, %2};" : "=l"(r) : "f"(lo), "f"(hi)); return r;
}
__device__ __forceinline__ void up2(u64 v, float& lo, float& hi) {
    asm("mov.b64 {%0, %1}, %2;" : "=f"(lo), "=f"(hi) : "l"(v));
}
__device__ __forceinline__ u64 f2fma(u64 a, u64 b, u64 c) {
    u64 d; asm("fma.rn.f32x2 %0, %1, %2, %3;" : "=l"(d) : "l"(a), "l"(b), "l"(c)); return d;
}
__device__ __forceinline__ u64 f2mul(u64 a, u64 b) {
    u64 d; asm("mul.rn.f32x2 %0, %1, %2;" : "=l"(d) : "l"(a), "l"(b)); return d;
}

#define SGNC 0x8000000080000000ull

// acc = acc (x) q  (Hamilton, acc on the left)
__device__ __forceinline__ void ham(u64& ar, u64& ai, u64& aj, u64& ak,
                                    u64 qr, u64 qi, u64 qj, u64 qk) {
    u64 nr = f2fma(ar, qr, f2fma(ai, qi ^ SGNC, f2fma(aj, qj ^ SGNC, f2mul(ak, qk ^ SGNC))));
    u64 ni = f2fma(ar, qi, f2fma(ai, qr,        f2fma(aj, qk,        f2mul(ak, qj ^ SGNC))));
    u64 nj = f2fma(ar, qj, f2fma(ai, qk ^ SGNC, f2fma(aj, qr,        f2mul(ak, qi))));
    u64 nk = f2fma(ar, qk, f2fma(ai, qj,        f2fma(aj, qi ^ SGNC, f2mul(ak, qr))));
    ar = nr; ai = ni; aj = nj; ak = nk;
}

// Build packed q-pair for one channel from {th,iv,jv,kv} and weight pair.
__device__ __forceinline__ void mkq(float4 t, u64 w2, float blo, float bhi,
                                    u64& qr, u64& qi, u64& qj, u64& qk) {
    float wlo, whi; up2(w2, wlo, whi);
    float t0 = fmaf(wlo, t.x, blo);
    float t1 = fmaf(whi, t.x, bhi);
    float s0, c0, s1, c1;
    __sincosf(t0, &s0, &c0);
    __sincosf(t1, &s1, &c1);
    u64 sin2 = pk2(s0, s1);
    qr = pk2(c0, c1);
    qi = f2mul(pk2(t.y, t.y), sin2);
    qj = f2mul(pk2(t.z, t.z), sin2);
    qk = f2mul(pk2(t.w, t.w), sin2);
}

__global__ __launch_bounds__(NTHREADS)
void qpu_kernel(const float* __restrict__ x, const float* __restrict__ w,
                const float* __restrict__ bias, float* __restrict__ out,
                int n_tokens)
{
    // sw[c][opair] = {w[2*opair][c], w[2*opair+1][c]}        (32 KB)
    __shared__ __align__(16) u64 sw[CIN][CIN];
    // tokv[g][c] = {th, iv, jv, kv}  (non-duplicated)        (4 KB)
    __shared__ __align__(16) float4 tokv[TPB_TOKENS][CIN];

    const int tid  = threadIdx.x;
    const int g    = tid >> 7;
    const int lt   = tid & 127;
    const int opair = ((lt >> 5) << 4) | (lt & 15);  // 0..63
    const int half  = (lt >> 4) & 1;

    for (int idx = tid; idx < CIN * CIN; idx += NTHREADS) {
        int c = idx >> 6, l = idx & 63;
        sw[c][l] = pk2(w[(2 * l) * CIN + c], w[(2 * l + 1) * CIN + c]);
    }

    const int tokIdx = blockIdx.x * TPB_TOKENS + g;

    if (tokIdx < n_tokens && lt < CIN) {
        const float* xp = x + (size_t)tokIdx * (4 * CIN);
        int c = lt;
        float r = xp[c];
        float i = xp[CIN + c];
        float j = xp[2 * CIN + c];
        float k = xp[3 * CIN + c];
        float inv = rsqrtf(fmaf(i, i, fmaf(j, j, fmaf(k, k, 1e-12f))));
        const float CLAMP = (float)(1.0 - 1e-6);
        r = fminf(fmaxf(r, -CLAMP), CLAMP);
        tokv[g][c] = make_float4(acosf(r), i * inv, j * inv, k * inv);
    }
    __syncthreads();

    if (tokIdx >= n_tokens) return;

    float blo, bhi;
    up2(((const u64*)bias)[opair], blo, bhi);

    // two independent chains: A = channels [cbase, cbase+16), B = [cbase+16, cbase+32)
    u64 a0r = pk2(1.0f, 1.0f), a0i = 0ull, a0j = 0ull, a0k = 0ull;
    u64 a1r = pk2(1.0f, 1.0f), a1i = 0ull, a1j = 0ull, a1k = 0ull;
    const int cbase = half << 5;

#pragma unroll 4
    for (int t = 0; t < 16; ++t) {
        const int ca = cbase + t;
        const int cb = cbase + 16 + t;
        float4 ta = tokv[g][ca];
        float4 tb = tokv[g][cb];
        u64 wa = sw[ca][opair];
        u64 wb = sw[cb][opair];

        u64 qr, qi, qj, qk;
        mkq(ta, wa, blo, bhi, qr, qi, qj, qk);
        u64 pr2, pi2, pj2, pk2v;
        mkq(tb, wb, blo, bhi, pr2, pi2, pj2, pk2v);

        ham(a0r, a0i, a0j, a0k, qr, qi, qj, qk);
        ham(a1r, a1i, a1j, a1k, pr2, pi2, pj2, pk2v);
    }

    // merge the two chains: a0 = a0 (x) a1
    ham(a0r, a0i, a0j, a0k, a1r, a1i, a1j, a1k);

    // ---- merge halves: P = P_half0 (x) P_half1 via shfl_xor(16) ----
    u64 br = __shfl_xor_sync(0xFFFFFFFFu, a0r, 16);
    u64 bi = __shfl_xor_sync(0xFFFFFFFFu, a0i, 16);
    u64 bj = __shfl_xor_sync(0xFFFFFFFFu, a0j, 16);
    u64 bk = __shfl_xor_sync(0xFFFFFFFFu, a0k, 16);

    u64 Ar = half ? br : a0r,  Ai = half ? bi : a0i;
    u64 Aj = half ? bj : a0j,  Ak = half ? bk : a0k;
    u64 Br = half ? a0r : br,  Bi = half ? a0i : bi;
    u64 Bj = half ? a0j : bj,  Bk = half ? a0k : bk;

    u64 pr = f2fma(Ar, Br, f2fma(Ai, Bi ^ SGNC, f2fma(Aj, Bj ^ SGNC, f2mul(Ak, Bk ^ SGNC))));
    u64 pi = f2fma(Ar, Bi, f2fma(Ai, Br,        f2fma(Aj, Bk,        f2mul(Ak, Bj ^ SGNC))));
    u64 pj = f2fma(Ar, Bj, f2fma(Ai, Bk ^ SGNC, f2fma(Aj, Br,        f2mul(Ak, Bi))));
    u64 pk_ = f2fma(Ar, Bk, f2fma(Ai, Bj,       f2fma(Aj, Bi ^ SGNC, f2mul(Ak, Br))));

    // ---- normalize + store ----
    u64 eps2 = pk2(1e-12f, 1e-12f);
    u64 n2 = f2fma(pr, pr, f2fma(pi, pi, f2fma(pj, pj, f2fma(pk_, pk_, eps2))));
    float n0, n1; up2(n2, n0, n1);
    u64 inv2 = pk2(rsqrtf(n0), rsqrtf(n1));

    float2* ob = (float2*)(out + (size_t)tokIdx * (4 * COUT));
    if (half == 0) {
        u64 v0 = f2mul(pr, inv2);
        u64 v1 = f2mul(pi, inv2);
        ob[opair]       = *(float2*)&v0;   // pr
        ob[64 + opair]  = *(float2*)&v1;   // pi
    } else {
        u64 v2 = f2mul(pj, inv2);
        u64 v3 = f2mul(pk_, inv2);
        ob[128 + opair] = *(float2*)&v2;   // pj
        ob[192 + opair] = *(float2*)&v3;   // pk
    }
}

extern "C" void kernel_launch(void* const* d_in, const int* in_sizes, int n_in,
                              void* d_out, int out_size) {
    const float* x = (const float*)d_in[0];
    const float* w = (const float*)d_in[1];
    const float* b = (const float*)d_in[2];
    int tokens = in_sizes[0] / (4 * CIN);
    int grid = (tokens + TPB_TOKENS - 1) / TPB_TOKENS;
    qpu_kernel<<<grid, NTHREADS>>>(x, w, b, (float*)d_out, tokens);
}